// round 13
// baseline (speedup 1.0000x reference)
#include <cuda_runtime.h>
#include <cuda_bf16.h>
#include <cstdint>
#include <math.h>

// NT-Xent contrastive loss, N=4096, D=1024, T=0.5 — bf16 mma.sync, symmetric-half GEMM.
// R13 = R10 (best: 178.7us) + final reduction fused into simloss via completion
// counter (last CTA reduces), dropping the third kernel launch.

#define TWO_N 8192
#define NHALF 4096
#define DIM   1024
#define INV_T 2.0f

__device__ __nv_bfloat16 g_zb[(size_t)TWO_N * DIM];
__device__ float g_denom[TWO_N];
__device__ float g_pos[TWO_N];
__device__ unsigned int g_done;

// ---------------------------------------------------------------- helpers
__device__ __forceinline__ uint32_t smem_u32(const void* p) {
    uint32_t a;
    asm("{ .reg .u64 t; cvta.to.shared.u64 t, %1; cvt.u32.u64 %0, t; }" : "=r"(a) : "l"(p));
    return a;
}

#define CP_ASYNC16(dst, src) \
    asm volatile("cp.async.cg.shared.global [%0], [%1], 16;" :: "r"(dst), "l"(src) : "memory")
#define CP_COMMIT() asm volatile("cp.async.commit_group;" ::: "memory")
#define CP_WAIT(n)  asm volatile("cp.async.wait_group %0;" :: "n"(n) : "memory")

__device__ __forceinline__ void ldsm4(uint32_t* r, uint32_t addr) {
    asm volatile("ldmatrix.sync.aligned.m8n8.x4.shared.b16 {%0,%1,%2,%3}, [%4];"
                 : "=r"(r[0]), "=r"(r[1]), "=r"(r[2]), "=r"(r[3]) : "r"(addr));
}

__device__ __forceinline__ void mma16816(float* c, const uint32_t* a, const uint32_t* b) {
    asm volatile("mma.sync.aligned.m16n8k16.row.col.f32.bf16.bf16.f32 "
                 "{%0,%1,%2,%3}, {%4,%5,%6,%7}, {%8,%9}, {%0,%1,%2,%3};"
                 : "+f"(c[0]), "+f"(c[1]), "+f"(c[2]), "+f"(c[3])
                 : "r"(a[0]), "r"(a[1]), "r"(a[2]), "r"(a[3]), "r"(b[0]), "r"(b[1]));
}

// Stage: A 128x64 bf16 (16KB) + B 128x64 bf16 (16KB), XOR swizzled
#define STAGE_BYTES 32768
#define AS_OFF(s)   ((s) * STAGE_BYTES)
#define BS_OFF(s)   ((s) * STAGE_BYTES + 16384)
#define SMEM_TOTAL  (3 * STAGE_BYTES)

// ---------------------------------------------------------------------------
// Warp-per-row L2-normalize (R10). Also resets the completion counter.
// ---------------------------------------------------------------------------
__global__ __launch_bounds__(256) void normalize_kernel(const float* __restrict__ ei,
                                                        const float* __restrict__ ej) {
    const int warp = (blockIdx.x * 256 + threadIdx.x) >> 5;
    const int lane = threadIdx.x & 31;
    const float* src = (warp < NHALF) ? (ei + (size_t)warp * DIM)
                                      : (ej + (size_t)(warp - NHALF) * DIM);
    float4 x[8];
    float s = 0.0f;
#pragma unroll
    for (int i = 0; i < 8; i++) {
        x[i] = ((const float4*)src)[lane + i * 32];
        s += x[i].x * x[i].x + x[i].y * x[i].y + x[i].z * x[i].z + x[i].w * x[i].w;
    }
#pragma unroll
    for (int o = 16; o > 0; o >>= 1) s += __shfl_xor_sync(0xffffffffu, s, o);
    const float inv = 1.0f / fmaxf(sqrtf(s), 1e-12f);

    uint32_t* dst = (uint32_t*)(g_zb + (size_t)warp * DIM);
#pragma unroll
    for (int i = 0; i < 8; i++) {
        __nv_bfloat162 a = __floats2bfloat162_rn(x[i].x * inv, x[i].y * inv);
        __nv_bfloat162 b = __floats2bfloat162_rn(x[i].z * inv, x[i].w * inv);
        uint2 pk = make_uint2(*(uint32_t*)&a, *(uint32_t*)&b);
        ((uint2*)dst)[lane + i * 32] = pk;
    }
    if (lane == 0) g_denom[warp] = 0.0f;
    if (blockIdx.x == 0 && threadIdx.x == 0) g_done = 0u;
}

// ---------------------------------------------------------------------------
// Symmetric fused GEMM+loss. Tile 128x128, 8 warps (2x4), warp tile 64x32.
// Grid 64x64; upper-triangle CTAs (tj<ti) bump the counter and exit. The LAST
// CTA to finish performs the final loss reduction and writes out[0].
// ---------------------------------------------------------------------------
__global__ __launch_bounds__(256, 2) void simloss_kernel(float* __restrict__ out) {
    const int ti = blockIdx.y;
    const int tj = blockIdx.x;
    const int tid  = threadIdx.x;

    extern __shared__ char smem[];
    __shared__ unsigned int s_rank;

    if (tj >= ti) {
        const bool diag = (ti == tj);
        const int row0 = ti * 128;
        const int col0 = tj * 128;

        const uint32_t sb = smem_u32(smem);
        const int wid  = tid >> 5;
        const int lane = tid & 31;
        const int wm   = wid >> 2;
        const int wn   = wid & 3;

        float acc[4][4][4];
#pragma unroll
        for (int mb = 0; mb < 4; mb++)
#pragma unroll
            for (int nb = 0; nb < 4; nb++)
#pragma unroll
                for (int q = 0; q < 4; q++) acc[mb][nb][q] = 0.0f;

        const int a_row = lane & 15;
        const int a_sel = lane >> 4;
        const int b_n   = (lane & 7) + ((lane >> 4) << 3);
        const int b_sel = (lane >> 3) & 1;

        auto load_stage = [&](int s, int kc) {
            const size_t k0 = (size_t)kc * 64;
#pragma unroll
            for (int i = 0; i < 8; i++) {
                const int idx = tid + i * 256;
                if (idx < 1024) {
                    const int r = idx >> 3, ch = idx & 7;
                    CP_ASYNC16(sb + AS_OFF(s) + r * 128 + ((ch ^ (r & 7)) << 4),
                               g_zb + (size_t)(row0 + r) * DIM + k0 + ch * 8);
                } else if (!diag) {
                    const int j = idx - 1024;
                    const int r = j >> 3, ch = j & 7;
                    CP_ASYNC16(sb + BS_OFF(s) + r * 128 + ((ch ^ (r & 7)) << 4),
                               g_zb + (size_t)(col0 + r) * DIM + k0 + ch * 8);
                }
            }
        };

        auto compute_stage = [&](int s) {
            const uint32_t as = sb + AS_OFF(s);
            const uint32_t bs = diag ? as : (sb + BS_OFF(s));
#pragma unroll
            for (int kk = 0; kk < 4; kk++) {
                uint32_t a[4][4], b[2][4];
#pragma unroll
                for (int mb = 0; mb < 4; mb++) {
                    const int r = wm * 64 + mb * 16 + a_row;
                    const int ch = kk * 2 + a_sel;
                    ldsm4(a[mb], as + r * 128 + ((ch ^ (r & 7)) << 4));
                }
#pragma unroll
                for (int nb2 = 0; nb2 < 2; nb2++) {
                    const int r = wn * 32 + nb2 * 16 + b_n;
                    const int ch = kk * 2 + b_sel;
                    ldsm4(b[nb2], bs + r * 128 + ((ch ^ (r & 7)) << 4));
                }
#pragma unroll
                for (int mb = 0; mb < 4; mb++)
#pragma unroll
                    for (int nb = 0; nb < 4; nb++)
                        mma16816(acc[mb][nb], a[mb], &b[nb >> 1][(nb & 1) * 2]);
            }
        };

        load_stage(0, 0); CP_COMMIT();
        load_stage(1, 1); CP_COMMIT();
        CP_WAIT(1);
        __syncthreads();

        for (int ks = 0; ks < 16; ks++) {
            compute_stage(ks % 3);
            if (ks + 2 < 16) {
                load_stage((ks + 2) % 3, ks + 2);
                CP_COMMIT();
                CP_WAIT(1);
                __syncthreads();
            } else if (ks + 1 < 16) {
                CP_WAIT(0);
                __syncthreads();
            }
        }

        // ------------------------- epilogue -------------------------
        __syncthreads();
        float* rowred = (float*)smem;
        float* colred = (float*)smem + 128;
        if (tid < 128) { rowred[tid] = 0.0f; colred[tid] = 0.0f; }
        __syncthreads();

        float colacc[4][2];
#pragma unroll
        for (int nb = 0; nb < 4; nb++) colacc[nb][0] = colacc[nb][1] = 0.0f;

#pragma unroll
        for (int mb = 0; mb < 4; mb++) {
            const int lrow = wm * 64 + mb * 16 + (lane >> 2);
            const int r_lo = row0 + lrow;
            const int r_hi = r_lo + 8;
            const int p_lo = (r_lo < NHALF) ? (r_lo + NHALF) : (r_lo - NHALF);
            const int p_hi = (r_hi < NHALF) ? (r_hi + NHALF) : (r_hi - NHALF);
            float slo = 0.0f, shi = 0.0f;
#pragma unroll
            for (int nb = 0; nb < 4; nb++) {
                const int c = col0 + wn * 32 + nb * 8 + (lane & 3) * 2;
                const float v0 = acc[mb][nb][0], v1 = acc[mb][nb][1];
                const float v2 = acc[mb][nb][2], v3 = acc[mb][nb][3];
                float e0 = __expf(v0 * INV_T), e1 = __expf(v1 * INV_T);
                float e2 = __expf(v2 * INV_T), e3 = __expf(v3 * INV_T);
                if (diag) {
                    if (c     == r_lo) e0 = 0.0f;
                    if (c + 1 == r_lo) e1 = 0.0f;
                    if (c     == r_hi) e2 = 0.0f;
                    if (c + 1 == r_hi) e3 = 0.0f;
                } else {
                    if (c     == p_lo) { g_pos[r_lo] = v0; g_pos[c]     = v0; }
                    if (c + 1 == p_lo) { g_pos[r_lo] = v1; g_pos[c + 1] = v1; }
                    if (c     == p_hi) { g_pos[r_hi] = v2; g_pos[c]     = v2; }
                    if (c + 1 == p_hi) { g_pos[r_hi] = v3; g_pos[c + 1] = v3; }
                }
                slo += e0 + e1;  shi += e2 + e3;
                colacc[nb][0] += e0 + e2;
                colacc[nb][1] += e1 + e3;
            }
            slo += __shfl_xor_sync(0xffffffffu, slo, 1);
            slo += __shfl_xor_sync(0xffffffffu, slo, 2);
            shi += __shfl_xor_sync(0xffffffffu, shi, 1);
            shi += __shfl_xor_sync(0xffffffffu, shi, 2);
            if ((lane & 3) == 0) {
                atomicAdd(&rowred[lrow], slo);
                atomicAdd(&rowred[lrow + 8], shi);
            }
        }

        if (!diag) {
#pragma unroll
            for (int nb = 0; nb < 4; nb++) {
#pragma unroll
                for (int p = 0; p < 2; p++) {
                    float cs = colacc[nb][p];
                    cs += __shfl_xor_sync(0xffffffffu, cs, 4);
                    cs += __shfl_xor_sync(0xffffffffu, cs, 8);
                    cs += __shfl_xor_sync(0xffffffffu, cs, 16);
                    if ((lane >> 2) == 0)
                        atomicAdd(&colred[wn * 32 + nb * 8 + (lane & 3) * 2 + p], cs);
                }
            }
        }

        __syncthreads();
        if (tid < 128) {
            atomicAdd(&g_denom[row0 + tid], rowred[tid]);
            if (!diag) atomicAdd(&g_denom[col0 + tid], colred[tid]);
        }
    }

    // ---------------- completion counter + fused final reduction ----------------
    __syncthreads();
    __threadfence();
    if (tid == 0) s_rank = atomicAdd(&g_done, 1u);
    __syncthreads();
    if (s_rank == 64u * 64u - 1u) {
        __threadfence();
        float v = 0.0f;
#pragma unroll
        for (int i = 0; i < 32; i++) {
            const int r = tid + i * 256;
            v += logf(g_denom[r]) - g_pos[r] * INV_T;
        }
#pragma unroll
        for (int o = 16; o > 0; o >>= 1) v += __shfl_xor_sync(0xffffffffu, v, o);
        float* ws = (float*)smem;
        if ((tid & 31) == 0) ws[tid >> 5] = v;
        __syncthreads();
        if (tid == 0) {
            float s = ws[0] + ws[1] + ws[2] + ws[3] + ws[4] + ws[5] + ws[6] + ws[7];
            out[0] = s * (1.0f / (float)TWO_N);
        }
    }
}

// ---------------------------------------------------------------------------
extern "C" void kernel_launch(void* const* d_in, const int* in_sizes, int n_in,
                              void* d_out, int out_size) {
    const float* emb_i = (const float*)d_in[0];
    const float* emb_j = (const float*)d_in[1];
    float* out = (float*)d_out;

    cudaFuncSetAttribute(simloss_kernel, cudaFuncAttributeMaxDynamicSharedMemorySize,
                         SMEM_TOTAL);

    normalize_kernel<<<TWO_N / 8, 256>>>(emb_i, emb_j);
    dim3 grid(64, 64);
    simloss_kernel<<<grid, 256, SMEM_TOTAL>>>(out);
}

// round 14
// speedup vs baseline: 1.2310x; 1.2310x over previous
#include <cuda_runtime.h>
#include <cuda_bf16.h>
#include <cstdint>
#include <math.h>

// NT-Xent contrastive loss, N=4096, D=1024, T=0.5 — bf16 mma.sync, symmetric-half GEMM.
// R14 = R10 (best: 178.7us) with the epilogue smem staging removed: shuffle-reduced
// row/col exp-sums go straight to g_denom via no-return global atomics (REDG),
// deleting 2 epilogue barriers + smem zeroing per tile. Mainloop byte-identical to R10.

#define TWO_N 8192
#define NHALF 4096
#define DIM   1024
#define INV_T 2.0f

__device__ __nv_bfloat16 g_zb[(size_t)TWO_N * DIM];
__device__ float g_denom[TWO_N];
__device__ float g_pos[TWO_N];

// ---------------------------------------------------------------- helpers
__device__ __forceinline__ uint32_t smem_u32(const void* p) {
    uint32_t a;
    asm("{ .reg .u64 t; cvta.to.shared.u64 t, %1; cvt.u32.u64 %0, t; }" : "=r"(a) : "l"(p));
    return a;
}

#define CP_ASYNC16(dst, src) \
    asm volatile("cp.async.cg.shared.global [%0], [%1], 16;" :: "r"(dst), "l"(src) : "memory")
#define CP_COMMIT() asm volatile("cp.async.commit_group;" ::: "memory")
#define CP_WAIT(n)  asm volatile("cp.async.wait_group %0;" :: "n"(n) : "memory")

__device__ __forceinline__ void ldsm4(uint32_t* r, uint32_t addr) {
    asm volatile("ldmatrix.sync.aligned.m8n8.x4.shared.b16 {%0,%1,%2,%3}, [%4];"
                 : "=r"(r[0]), "=r"(r[1]), "=r"(r[2]), "=r"(r[3]) : "r"(addr));
}

__device__ __forceinline__ void mma16816(float* c, const uint32_t* a, const uint32_t* b) {
    asm volatile("mma.sync.aligned.m16n8k16.row.col.f32.bf16.bf16.f32 "
                 "{%0,%1,%2,%3}, {%4,%5,%6,%7}, {%8,%9}, {%0,%1,%2,%3};"
                 : "+f"(c[0]), "+f"(c[1]), "+f"(c[2]), "+f"(c[3])
                 : "r"(a[0]), "r"(a[1]), "r"(a[2]), "r"(a[3]), "r"(b[0]), "r"(b[1]));
}

// Stage: A 128x64 bf16 (16KB) + B 128x64 bf16 (16KB), XOR swizzled
#define STAGE_BYTES 32768
#define AS_OFF(s)   ((s) * STAGE_BYTES)
#define BS_OFF(s)   ((s) * STAGE_BYTES + 16384)
#define SMEM_TOTAL  (3 * STAGE_BYTES)

// ---------------------------------------------------------------------------
// Warp-per-row L2-normalize (R10).
// ---------------------------------------------------------------------------
__global__ __launch_bounds__(256) void normalize_kernel(const float* __restrict__ ei,
                                                        const float* __restrict__ ej) {
    const int warp = (blockIdx.x * 256 + threadIdx.x) >> 5;
    const int lane = threadIdx.x & 31;
    const float* src = (warp < NHALF) ? (ei + (size_t)warp * DIM)
                                      : (ej + (size_t)(warp - NHALF) * DIM);
    float4 x[8];
    float s = 0.0f;
#pragma unroll
    for (int i = 0; i < 8; i++) {
        x[i] = ((const float4*)src)[lane + i * 32];
        s += x[i].x * x[i].x + x[i].y * x[i].y + x[i].z * x[i].z + x[i].w * x[i].w;
    }
#pragma unroll
    for (int o = 16; o > 0; o >>= 1) s += __shfl_xor_sync(0xffffffffu, s, o);
    const float inv = 1.0f / fmaxf(sqrtf(s), 1e-12f);

    uint32_t* dst = (uint32_t*)(g_zb + (size_t)warp * DIM);
#pragma unroll
    for (int i = 0; i < 8; i++) {
        __nv_bfloat162 a = __floats2bfloat162_rn(x[i].x * inv, x[i].y * inv);
        __nv_bfloat162 b = __floats2bfloat162_rn(x[i].z * inv, x[i].w * inv);
        uint2 pk = make_uint2(*(uint32_t*)&a, *(uint32_t*)&b);
        ((uint2*)dst)[lane + i * 32] = pk;
    }
    if (lane == 0) g_denom[warp] = 0.0f;
}

// ---------------------------------------------------------------------------
// Symmetric fused GEMM+loss. Tile 128x128, 8 warps (2x4), warp tile 64x32.
// Grid 64x64; CTAs with col-tile < row-tile exit immediately. (R5/R10 config.)
// Epilogue: direct global REDG, no smem staging.
// ---------------------------------------------------------------------------
__global__ __launch_bounds__(256, 2) void simloss_kernel() {
    const int ti = blockIdx.y;
    const int tj = blockIdx.x;
    if (tj < ti) return;
    const bool diag = (ti == tj);
    const int row0 = ti * 128;
    const int col0 = tj * 128;

    extern __shared__ char smem[];
    const uint32_t sb = smem_u32(smem);
    const int tid  = threadIdx.x;
    const int wid  = tid >> 5;
    const int lane = tid & 31;
    const int wm   = wid >> 2;
    const int wn   = wid & 3;

    float acc[4][4][4];
#pragma unroll
    for (int mb = 0; mb < 4; mb++)
#pragma unroll
        for (int nb = 0; nb < 4; nb++)
#pragma unroll
            for (int q = 0; q < 4; q++) acc[mb][nb][q] = 0.0f;

    const int a_row = lane & 15;
    const int a_sel = lane >> 4;
    const int b_n   = (lane & 7) + ((lane >> 4) << 3);
    const int b_sel = (lane >> 3) & 1;

    auto load_stage = [&](int s, int kc) {
        const size_t k0 = (size_t)kc * 64;
#pragma unroll
        for (int i = 0; i < 8; i++) {
            const int idx = tid + i * 256;
            if (idx < 1024) {
                const int r = idx >> 3, ch = idx & 7;
                CP_ASYNC16(sb + AS_OFF(s) + r * 128 + ((ch ^ (r & 7)) << 4),
                           g_zb + (size_t)(row0 + r) * DIM + k0 + ch * 8);
            } else if (!diag) {
                const int j = idx - 1024;
                const int r = j >> 3, ch = j & 7;
                CP_ASYNC16(sb + BS_OFF(s) + r * 128 + ((ch ^ (r & 7)) << 4),
                           g_zb + (size_t)(col0 + r) * DIM + k0 + ch * 8);
            }
        }
    };

    auto compute_stage = [&](int s) {
        const uint32_t as = sb + AS_OFF(s);
        const uint32_t bs = diag ? as : (sb + BS_OFF(s));
#pragma unroll
        for (int kk = 0; kk < 4; kk++) {
            uint32_t a[4][4], b[2][4];
#pragma unroll
            for (int mb = 0; mb < 4; mb++) {
                const int r = wm * 64 + mb * 16 + a_row;
                const int ch = kk * 2 + a_sel;
                ldsm4(a[mb], as + r * 128 + ((ch ^ (r & 7)) << 4));
            }
#pragma unroll
            for (int nb2 = 0; nb2 < 2; nb2++) {
                const int r = wn * 32 + nb2 * 16 + b_n;
                const int ch = kk * 2 + b_sel;
                ldsm4(b[nb2], bs + r * 128 + ((ch ^ (r & 7)) << 4));
            }
#pragma unroll
            for (int mb = 0; mb < 4; mb++)
#pragma unroll
                for (int nb = 0; nb < 4; nb++)
                    mma16816(acc[mb][nb], a[mb], &b[nb >> 1][(nb & 1) * 2]);
        }
    };

    load_stage(0, 0); CP_COMMIT();
    load_stage(1, 1); CP_COMMIT();
    CP_WAIT(1);
    __syncthreads();

    for (int ks = 0; ks < 16; ks++) {
        compute_stage(ks % 3);
        if (ks + 2 < 16) {
            load_stage((ks + 2) % 3, ks + 2);
            CP_COMMIT();
            CP_WAIT(1);
            __syncthreads();
        } else if (ks + 1 < 16) {
            CP_WAIT(0);
            __syncthreads();
        }
    }

    // ---------------- epilogue: direct global reduction (no smem) ----------------
    float colacc[4][2];
#pragma unroll
    for (int nb = 0; nb < 4; nb++) colacc[nb][0] = colacc[nb][1] = 0.0f;

#pragma unroll
    for (int mb = 0; mb < 4; mb++) {
        const int lrow = wm * 64 + mb * 16 + (lane >> 2);
        const int r_lo = row0 + lrow;
        const int r_hi = r_lo + 8;
        const int p_lo = (r_lo < NHALF) ? (r_lo + NHALF) : (r_lo - NHALF);
        const int p_hi = (r_hi < NHALF) ? (r_hi + NHALF) : (r_hi - NHALF);
        float slo = 0.0f, shi = 0.0f;
#pragma unroll
        for (int nb = 0; nb < 4; nb++) {
            const int c = col0 + wn * 32 + nb * 8 + (lane & 3) * 2;
            const float v0 = acc[mb][nb][0], v1 = acc[mb][nb][1];
            const float v2 = acc[mb][nb][2], v3 = acc[mb][nb][3];
            float e0 = __expf(v0 * INV_T), e1 = __expf(v1 * INV_T);
            float e2 = __expf(v2 * INV_T), e3 = __expf(v3 * INV_T);
            if (diag) {
                if (c     == r_lo) e0 = 0.0f;
                if (c + 1 == r_lo) e1 = 0.0f;
                if (c     == r_hi) e2 = 0.0f;
                if (c + 1 == r_hi) e3 = 0.0f;
            } else {
                if (c     == p_lo) { g_pos[r_lo] = v0; g_pos[c]     = v0; }
                if (c + 1 == p_lo) { g_pos[r_lo] = v1; g_pos[c + 1] = v1; }
                if (c     == p_hi) { g_pos[r_hi] = v2; g_pos[c]     = v2; }
                if (c + 1 == p_hi) { g_pos[r_hi] = v3; g_pos[c + 1] = v3; }
            }
            slo += e0 + e1;  shi += e2 + e3;
            colacc[nb][0] += e0 + e2;
            colacc[nb][1] += e1 + e3;
        }
        slo += __shfl_xor_sync(0xffffffffu, slo, 1);
        slo += __shfl_xor_sync(0xffffffffu, slo, 2);
        shi += __shfl_xor_sync(0xffffffffu, shi, 1);
        shi += __shfl_xor_sync(0xffffffffu, shi, 2);
        if ((lane & 3) == 0) {
            atomicAdd(&g_denom[r_lo], slo);
            atomicAdd(&g_denom[r_hi], shi);
        }
    }

    if (!diag) {
#pragma unroll
        for (int nb = 0; nb < 4; nb++) {
#pragma unroll
            for (int p = 0; p < 2; p++) {
                float cs = colacc[nb][p];
                cs += __shfl_xor_sync(0xffffffffu, cs, 4);
                cs += __shfl_xor_sync(0xffffffffu, cs, 8);
                cs += __shfl_xor_sync(0xffffffffu, cs, 16);
                if ((lane >> 2) == 0)
                    atomicAdd(&g_denom[col0 + wn * 32 + nb * 8 + (lane & 3) * 2 + p], cs);
            }
        }
    }
}

// ---------------------------------------------------------------------------
// Single-block final reduction (separate launch — merged variant regressed).
// ---------------------------------------------------------------------------
__global__ __launch_bounds__(1024) void loss_final_kernel(float* __restrict__ out) {
    const int t = threadIdx.x;
    float v = 0.0f;
#pragma unroll
    for (int i = 0; i < 8; i++) {
        const int r = t + i * 1024;
        v += logf(g_denom[r]) - g_pos[r] * INV_T;
    }
#pragma unroll
    for (int o = 16; o > 0; o >>= 1) v += __shfl_xor_sync(0xffffffffu, v, o);
    __shared__ float ws[32];
    if ((t & 31) == 0) ws[t >> 5] = v;
    __syncthreads();
    if (t < 32) {
        float s = ws[t];
#pragma unroll
        for (int o = 16; o > 0; o >>= 1) s += __shfl_xor_sync(0xffffffffu, s, o);
        if (t == 0) out[0] = s * (1.0f / (float)TWO_N);
    }
}

// ---------------------------------------------------------------------------
extern "C" void kernel_launch(void* const* d_in, const int* in_sizes, int n_in,
                              void* d_out, int out_size) {
    const float* emb_i = (const float*)d_in[0];
    const float* emb_j = (const float*)d_in[1];
    float* out = (float*)d_out;

    cudaFuncSetAttribute(simloss_kernel, cudaFuncAttributeMaxDynamicSharedMemorySize,
                         SMEM_TOTAL);

    normalize_kernel<<<TWO_N / 8, 256>>>(emb_i, emb_j);
    dim3 grid(64, 64);
    simloss_kernel<<<grid, 256, SMEM_TOTAL>>>();
    loss_final_kernel<<<1, 1024>>>(out);
}

// round 15
// speedup vs baseline: 1.2456x; 1.0119x over previous
#include <cuda_runtime.h>
#include <cuda_bf16.h>
#include <cstdint>
#include <math.h>

// NT-Xent contrastive loss, N=4096, D=1024, T=0.5 — bf16 mma.sync, symmetric-half GEMM.
// R15 = R14 (best: 174.8us) + positive-capture gated to the 32 tiles with tj==ti+32
// + 16B stores in normalize. Mainloop byte-identical to R14.

#define TWO_N 8192
#define NHALF 4096
#define DIM   1024
#define INV_T 2.0f

__device__ __nv_bfloat16 g_zb[(size_t)TWO_N * DIM];
__device__ float g_denom[TWO_N];
__device__ float g_pos[TWO_N];

// ---------------------------------------------------------------- helpers
__device__ __forceinline__ uint32_t smem_u32(const void* p) {
    uint32_t a;
    asm("{ .reg .u64 t; cvta.to.shared.u64 t, %1; cvt.u32.u64 %0, t; }" : "=r"(a) : "l"(p));
    return a;
}

#define CP_ASYNC16(dst, src) \
    asm volatile("cp.async.cg.shared.global [%0], [%1], 16;" :: "r"(dst), "l"(src) : "memory")
#define CP_COMMIT() asm volatile("cp.async.commit_group;" ::: "memory")
#define CP_WAIT(n)  asm volatile("cp.async.wait_group %0;" :: "n"(n) : "memory")

__device__ __forceinline__ void ldsm4(uint32_t* r, uint32_t addr) {
    asm volatile("ldmatrix.sync.aligned.m8n8.x4.shared.b16 {%0,%1,%2,%3}, [%4];"
                 : "=r"(r[0]), "=r"(r[1]), "=r"(r[2]), "=r"(r[3]) : "r"(addr));
}

__device__ __forceinline__ void mma16816(float* c, const uint32_t* a, const uint32_t* b) {
    asm volatile("mma.sync.aligned.m16n8k16.row.col.f32.bf16.bf16.f32 "
                 "{%0,%1,%2,%3}, {%4,%5,%6,%7}, {%8,%9}, {%0,%1,%2,%3};"
                 : "+f"(c[0]), "+f"(c[1]), "+f"(c[2]), "+f"(c[3])
                 : "r"(a[0]), "r"(a[1]), "r"(a[2]), "r"(a[3]), "r"(b[0]), "r"(b[1]));
}

// Stage: A 128x64 bf16 (16KB) + B 128x64 bf16 (16KB), XOR swizzled
#define STAGE_BYTES 32768
#define AS_OFF(s)   ((s) * STAGE_BYTES)
#define BS_OFF(s)   ((s) * STAGE_BYTES + 16384)
#define SMEM_TOTAL  (3 * STAGE_BYTES)

// ---------------------------------------------------------------------------
// Warp-per-row L2-normalize; 16B stores.
// ---------------------------------------------------------------------------
__global__ __launch_bounds__(256) void normalize_kernel(const float* __restrict__ ei,
                                                        const float* __restrict__ ej) {
    const int warp = (blockIdx.x * 256 + threadIdx.x) >> 5;
    const int lane = threadIdx.x & 31;
    const float* src = (warp < NHALF) ? (ei + (size_t)warp * DIM)
                                      : (ej + (size_t)(warp - NHALF) * DIM);
    float4 x[8];
    float s = 0.0f;
#pragma unroll
    for (int i = 0; i < 8; i++) {
        x[i] = ((const float4*)src)[lane + i * 32];
        s += x[i].x * x[i].x + x[i].y * x[i].y + x[i].z * x[i].z + x[i].w * x[i].w;
    }
#pragma unroll
    for (int o = 16; o > 0; o >>= 1) s += __shfl_xor_sync(0xffffffffu, s, o);
    const float inv = 1.0f / fmaxf(sqrtf(s), 1e-12f);

    uint4* dst = (uint4*)(g_zb + (size_t)warp * DIM);
#pragma unroll
    for (int i = 0; i < 4; i++) {
        __nv_bfloat162 a0 = __floats2bfloat162_rn(x[2*i].x * inv, x[2*i].y * inv);
        __nv_bfloat162 b0 = __floats2bfloat162_rn(x[2*i].z * inv, x[2*i].w * inv);
        __nv_bfloat162 a1 = __floats2bfloat162_rn(x[2*i+1].x * inv, x[2*i+1].y * inv);
        __nv_bfloat162 b1 = __floats2bfloat162_rn(x[2*i+1].z * inv, x[2*i+1].w * inv);
        // x[2i] is float4 #(lane + 2i*32), x[2i+1] is #(lane + (2i+1)*32):
        // NOT adjacent — store each 8B half to its own slot as a uint2 pair packed
        // into one 16B store only when adjacent. They aren't, so store as two uint2.
        ((uint2*)dst)[lane + (2*i)     * 32] = make_uint2(*(uint32_t*)&a0, *(uint32_t*)&b0);
        ((uint2*)dst)[lane + (2*i + 1) * 32] = make_uint2(*(uint32_t*)&a1, *(uint32_t*)&b1);
    }
    if (lane == 0) g_denom[warp] = 0.0f;
}

// ---------------------------------------------------------------------------
// Symmetric fused GEMM+loss. Tile 128x128, 8 warps (2x4), warp tile 64x32.
// Grid 64x64; CTAs with col-tile < row-tile exit immediately.
// Epilogue: direct global REDG; positive capture only when tj == ti+32.
// ---------------------------------------------------------------------------
__global__ __launch_bounds__(256, 2) void simloss_kernel() {
    const int ti = blockIdx.y;
    const int tj = blockIdx.x;
    if (tj < ti) return;
    const bool diag   = (ti == tj);
    const bool haspos = (tj == ti + 32);
    const int row0 = ti * 128;
    const int col0 = tj * 128;

    extern __shared__ char smem[];
    const uint32_t sb = smem_u32(smem);
    const int tid  = threadIdx.x;
    const int wid  = tid >> 5;
    const int lane = tid & 31;
    const int wm   = wid >> 2;
    const int wn   = wid & 3;

    float acc[4][4][4];
#pragma unroll
    for (int mb = 0; mb < 4; mb++)
#pragma unroll
        for (int nb = 0; nb < 4; nb++)
#pragma unroll
            for (int q = 0; q < 4; q++) acc[mb][nb][q] = 0.0f;

    const int a_row = lane & 15;
    const int a_sel = lane >> 4;
    const int b_n   = (lane & 7) + ((lane >> 4) << 3);
    const int b_sel = (lane >> 3) & 1;

    auto load_stage = [&](int s, int kc) {
        const size_t k0 = (size_t)kc * 64;
#pragma unroll
        for (int i = 0; i < 8; i++) {
            const int idx = tid + i * 256;
            if (idx < 1024) {
                const int r = idx >> 3, ch = idx & 7;
                CP_ASYNC16(sb + AS_OFF(s) + r * 128 + ((ch ^ (r & 7)) << 4),
                           g_zb + (size_t)(row0 + r) * DIM + k0 + ch * 8);
            } else if (!diag) {
                const int j = idx - 1024;
                const int r = j >> 3, ch = j & 7;
                CP_ASYNC16(sb + BS_OFF(s) + r * 128 + ((ch ^ (r & 7)) << 4),
                           g_zb + (size_t)(col0 + r) * DIM + k0 + ch * 8);
            }
        }
    };

    auto compute_stage = [&](int s) {
        const uint32_t as = sb + AS_OFF(s);
        const uint32_t bs = diag ? as : (sb + BS_OFF(s));
#pragma unroll
        for (int kk = 0; kk < 4; kk++) {
            uint32_t a[4][4], b[2][4];
#pragma unroll
            for (int mb = 0; mb < 4; mb++) {
                const int r = wm * 64 + mb * 16 + a_row;
                const int ch = kk * 2 + a_sel;
                ldsm4(a[mb], as + r * 128 + ((ch ^ (r & 7)) << 4));
            }
#pragma unroll
            for (int nb2 = 0; nb2 < 2; nb2++) {
                const int r = wn * 32 + nb2 * 16 + b_n;
                const int ch = kk * 2 + b_sel;
                ldsm4(b[nb2], bs + r * 128 + ((ch ^ (r & 7)) << 4));
            }
#pragma unroll
            for (int mb = 0; mb < 4; mb++)
#pragma unroll
                for (int nb = 0; nb < 4; nb++)
                    mma16816(acc[mb][nb], a[mb], &b[nb >> 1][(nb & 1) * 2]);
        }
    };

    load_stage(0, 0); CP_COMMIT();
    load_stage(1, 1); CP_COMMIT();
    CP_WAIT(1);
    __syncthreads();

    for (int ks = 0; ks < 16; ks++) {
        compute_stage(ks % 3);
        if (ks + 2 < 16) {
            load_stage((ks + 2) % 3, ks + 2);
            CP_COMMIT();
            CP_WAIT(1);
            __syncthreads();
        } else if (ks + 1 < 16) {
            CP_WAIT(0);
            __syncthreads();
        }
    }

    // ---------------- epilogue: direct global reduction (no smem) ----------------
    float colacc[4][2];
#pragma unroll
    for (int nb = 0; nb < 4; nb++) colacc[nb][0] = colacc[nb][1] = 0.0f;

#pragma unroll
    for (int mb = 0; mb < 4; mb++) {
        const int lrow = wm * 64 + mb * 16 + (lane >> 2);
        const int r_lo = row0 + lrow;
        const int r_hi = r_lo + 8;
        float slo = 0.0f, shi = 0.0f;
#pragma unroll
        for (int nb = 0; nb < 4; nb++) {
            const int c = col0 + wn * 32 + nb * 8 + (lane & 3) * 2;
            const float v0 = acc[mb][nb][0], v1 = acc[mb][nb][1];
            const float v2 = acc[mb][nb][2], v3 = acc[mb][nb][3];
            float e0 = __expf(v0 * INV_T), e1 = __expf(v1 * INV_T);
            float e2 = __expf(v2 * INV_T), e3 = __expf(v3 * INV_T);
            if (diag) {
                if (c     == r_lo) e0 = 0.0f;
                if (c + 1 == r_lo) e1 = 0.0f;
                if (c     == r_hi) e2 = 0.0f;
                if (c + 1 == r_hi) e3 = 0.0f;
            }
            if (haspos) {
                // positives only in tiles tj==ti+32: pcol = r + NHALF (rows < NHALF here)
                const int p_lo = r_lo + NHALF;
                const int p_hi = r_hi + NHALF;
                if (c     == p_lo) { g_pos[r_lo] = v0; g_pos[c]     = v0; }
                if (c + 1 == p_lo) { g_pos[r_lo] = v1; g_pos[c + 1] = v1; }
                if (c     == p_hi) { g_pos[r_hi] = v2; g_pos[c]     = v2; }
                if (c + 1 == p_hi) { g_pos[r_hi] = v3; g_pos[c + 1] = v3; }
            }
            slo += e0 + e1;  shi += e2 + e3;
            colacc[nb][0] += e0 + e2;
            colacc[nb][1] += e1 + e3;
        }
        slo += __shfl_xor_sync(0xffffffffu, slo, 1);
        slo += __shfl_xor_sync(0xffffffffu, slo, 2);
        shi += __shfl_xor_sync(0xffffffffu, shi, 1);
        shi += __shfl_xor_sync(0xffffffffu, shi, 2);
        if ((lane & 3) == 0) {
            atomicAdd(&g_denom[r_lo], slo);
            atomicAdd(&g_denom[r_hi], shi);
        }
    }

    if (!diag) {
#pragma unroll
        for (int nb = 0; nb < 4; nb++) {
#pragma unroll
            for (int p = 0; p < 2; p++) {
                float cs = colacc[nb][p];
                cs += __shfl_xor_sync(0xffffffffu, cs, 4);
                cs += __shfl_xor_sync(0xffffffffu, cs, 8);
                cs += __shfl_xor_sync(0xffffffffu, cs, 16);
                if ((lane >> 2) == 0)
                    atomicAdd(&g_denom[col0 + wn * 32 + nb * 8 + (lane & 3) * 2 + p], cs);
            }
        }
    }
}

// ---------------------------------------------------------------------------
// Single-block final reduction (separate launch — merged variant regressed).
// ---------------------------------------------------------------------------
__global__ __launch_bounds__(1024) void loss_final_kernel(float* __restrict__ out) {
    const int t = threadIdx.x;
    float v = 0.0f;
#pragma unroll
    for (int i = 0; i < 8; i++) {
        const int r = t + i * 1024;
        v += logf(g_denom[r]) - g_pos[r] * INV_T;
    }
#pragma unroll
    for (int o = 16; o > 0; o >>= 1) v += __shfl_xor_sync(0xffffffffu, v, o);
    __shared__ float ws[32];
    if ((t & 31) == 0) ws[t >> 5] = v;
    __syncthreads();
    if (t < 32) {
        float s = ws[t];
#pragma unroll
        for (int o = 16; o > 0; o >>= 1) s += __shfl_xor_sync(0xffffffffu, s, o);
        if (t == 0) out[0] = s * (1.0f / (float)TWO_N);
    }
}

// ---------------------------------------------------------------------------
extern "C" void kernel_launch(void* const* d_in, const int* in_sizes, int n_in,
                              void* d_out, int out_size) {
    const float* emb_i = (const float*)d_in[0];
    const float* emb_j = (const float*)d_in[1];
    float* out = (float*)d_out;

    cudaFuncSetAttribute(simloss_kernel, cudaFuncAttributeMaxDynamicSharedMemorySize,
                         SMEM_TOTAL);

    normalize_kernel<<<TWO_N / 8, 256>>>(emb_i, emb_j);
    dim3 grid(64, 64);
    simloss_kernel<<<grid, 256, SMEM_TOTAL>>>();
    loss_final_kernel<<<1, 1024>>>(out);
}